// round 1
// baseline (speedup 1.0000x reference)
#include <cuda_runtime.h>
#include <math.h>

#define Bb 4
#define Ss 1024
#define Dd 512
#define Hh 8
#define DKk 64
#define Mrows 4096   // B*S

// ---------------- scratch (no allocations allowed) ----------------
__device__ float g_qp[Mrows * Dd];
__device__ float g_kp[Mrows * Dd];
__device__ float g_vp[Mrows * Dd];
__device__ float g_op[Mrows * Dd];
__device__ float g_freq[32];

// ---------------- RoPE frequency table ----------------
__global__ void freq_init_kernel() {
    int t = threadIdx.x;
    if (t < 32) {
        // inv_freq[t] = 10000^(-(2t)/64), computed in double for best fp32 round
        g_freq[t] = (float)exp(-((double)(2 * t) / 64.0) * log(10000.0));
    }
}

// ---------------- generic GEMM: C[M,N] = A[M,K] @ W[N,K]^T + bias ----------------
// M=4096, N=512, K=512 fixed. 64x64 tile, BK=16, 256 threads, 4x4 microtile.
__global__ __launch_bounds__(256) void gemm_bias_kernel(
    const float* __restrict__ A, const float* __restrict__ W,
    const float* __restrict__ bias, float* __restrict__ C) {
    __shared__ __align__(16) float As[16 * 68];
    __shared__ __align__(16) float Bs[16 * 68];
    const int tid = threadIdx.x;
    const int ty = tid >> 4, tx = tid & 15;
    const int rowBase = blockIdx.y << 6;
    const int colBase = blockIdx.x << 6;
    float acc[4][4] = {};
    for (int kt = 0; kt < 512; kt += 16) {
#pragma unroll
        for (int e = 0; e < 4; e++) {
            int idx = tid + (e << 8);
            int r = idx >> 4, kq = idx & 15;
            As[kq * 68 + r] = A[(size_t)(rowBase + r) * 512 + kt + kq];
            Bs[kq * 68 + r] = W[(size_t)(colBase + r) * 512 + kt + kq];
        }
        __syncthreads();
#pragma unroll
        for (int kk = 0; kk < 16; kk++) {
            float4 av = *(const float4*)&As[kk * 68 + (ty << 2)];
            float4 bv = *(const float4*)&Bs[kk * 68 + (tx << 2)];
            acc[0][0] += av.x * bv.x; acc[0][1] += av.x * bv.y;
            acc[0][2] += av.x * bv.z; acc[0][3] += av.x * bv.w;
            acc[1][0] += av.y * bv.x; acc[1][1] += av.y * bv.y;
            acc[1][2] += av.y * bv.z; acc[1][3] += av.y * bv.w;
            acc[2][0] += av.z * bv.x; acc[2][1] += av.z * bv.y;
            acc[2][2] += av.z * bv.z; acc[2][3] += av.z * bv.w;
            acc[3][0] += av.w * bv.x; acc[3][1] += av.w * bv.y;
            acc[3][2] += av.w * bv.z; acc[3][3] += av.w * bv.w;
        }
        __syncthreads();
    }
#pragma unroll
    for (int i = 0; i < 4; i++) {
        int row = rowBase + (ty << 2) + i;
#pragma unroll
        for (int j = 0; j < 4; j++) {
            int col = colBase + (tx << 2) + j;
            C[(size_t)row * 512 + col] = acc[i][j] + bias[col];
        }
    }
}

// ---------------- RoPE in place on [B*S, D] projected q/k ----------------
__global__ __launch_bounds__(256) void rope_kernel(float* qp, float* kp) {
    int idx = blockIdx.x * 256 + threadIdx.x;   // 2 * 4096 * 256 threads
    float* x = (idx >= (Mrows * 256)) ? kp : qp;
    int rem = idx & (Mrows * 256 - 1);
    int row = rem >> 8;        // b*S + s
    int pr = rem & 255;        // pair index within row: h*32 + t
    int s = row & (Ss - 1);
    int t = pr & 31;
    int h = pr >> 5;
    float ang = (float)s * g_freq[t];
    float sv, cv;
    sincosf(ang, &sv, &cv);
    size_t base = (size_t)row * Dd + (h << 6) + (t << 1);
    float x0 = x[base], x1 = x[base + 1];
    x[base]     = x0 * cv - x1 * sv;
    x[base + 1] = x1 * cv + x0 * sv;
}

// ---------------- fused attention ----------------
// block = 16 query rows of one (b,h). 256 threads.
// smem: Ssm[16][1024] scores/attn, Psm[16][1024] exp scratch, Qs[16][64], KV union.
__global__ __launch_bounds__(256) void attn_kernel(
    const float* __restrict__ qp, const float* __restrict__ kp,
    const float* __restrict__ vp, const float* __restrict__ gammas,
    float* __restrict__ attn_out, float* __restrict__ op) {
    extern __shared__ float sm[];
    float* Ssm = sm;                 // 16*1024
    float* Psm = sm + 16 * 1024;     // 16*1024
    float* Qs  = sm + 32 * 1024;     // 16*64
    float* KVs = Qs + 16 * 64;       // 8320 floats (union: KsT[64][129] / Vs[128][65])

    const int tid = threadIdx.x;
    const int bh = blockIdx.y, b = bh >> 3, h = bh & 7;
    const int i0 = blockIdx.x << 4;
    const int r4 = tid >> 6, c = tid & 63;
    const int jtMax = (i0 + 15) >> 7;

    // load+scale Q tile
    for (int e = tid; e < 16 * 64; e += 256) {
        int r = e >> 6, dk = e & 63;
        Qs[e] = qp[(size_t)((b << 10) + i0 + r) * Dd + (h << 6) + dk] * 0.125f;
    }
    __syncthreads();

    // ---- scores = Q K^T (scaled), 128-wide j tiles ----
    for (int jt = 0; jt <= jtMax; jt++) {
        int j0 = jt << 7;
        for (int e = tid; e < 128 * 64; e += 256) {
            int j = e >> 6, dk = e & 63;
            KVs[dk * 129 + j] = kp[(size_t)((b << 10) + j0 + j) * Dd + (h << 6) + dk];
        }
        __syncthreads();
        float a0 = 0, a1 = 0, a2 = 0, a3 = 0, a4 = 0, a5 = 0, a6 = 0, a7 = 0;
#pragma unroll
        for (int kk = 0; kk < 64; kk++) {
            float k0 = KVs[kk * 129 + c];
            float k1 = KVs[kk * 129 + c + 64];
            float q0 = Qs[r4 * 64 + kk];
            float q1 = Qs[(r4 + 4) * 64 + kk];
            float q2 = Qs[(r4 + 8) * 64 + kk];
            float q3 = Qs[(r4 + 12) * 64 + kk];
            a0 += q0 * k0; a1 += q0 * k1;
            a2 += q1 * k0; a3 += q1 * k1;
            a4 += q2 * k0; a5 += q2 * k1;
            a6 += q3 * k0; a7 += q3 * k1;
        }
        Ssm[r4 * 1024 + j0 + c] = a0;          Ssm[r4 * 1024 + j0 + c + 64] = a1;
        Ssm[(r4 + 4) * 1024 + j0 + c] = a2;    Ssm[(r4 + 4) * 1024 + j0 + c + 64] = a3;
        Ssm[(r4 + 8) * 1024 + j0 + c] = a4;    Ssm[(r4 + 8) * 1024 + j0 + c + 64] = a5;
        Ssm[(r4 + 12) * 1024 + j0 + c] = a6;   Ssm[(r4 + 12) * 1024 + j0 + c + 64] = a7;
        __syncthreads();
    }

    // ---- row phase: softmax1, cumsum, decay gate, ALiBi, softmax2, attn write ----
    const int warp = tid >> 5, lane = tid & 31;
    const float gamma = gammas[h];
    const float g = -(fmaxf(gamma, 0.0f) + log1pf(expf(-fabsf(gamma))));  // -softplus
    const float g2 = g * g;
    const float slope = exp2f(-(float)(h + 1));
    const int jpad = (jtMax + 1) << 7;

    for (int rr = 0; rr < 2; rr++) {
        int r = (warp << 1) + rr;
        int gi = i0 + r;
        int n = gi + 1;
        float* Srow = Ssm + (r << 10);
        float* Prow = Psm + (r << 10);

        // max
        float mx = -3.0e38f;
        for (int j = lane; j < n; j += 32) mx = fmaxf(mx, Srow[j]);
#pragma unroll
        for (int o = 16; o; o >>= 1) mx = fmaxf(mx, __shfl_xor_sync(0xffffffffu, mx, o));
        // exp + sum (store exp in Prow)
        float se = 0.0f;
        for (int j = lane; j < n; j += 32) {
            float e = __expf(Srow[j] - mx);
            Prow[j] = e; se += e;
        }
#pragma unroll
        for (int o = 16; o; o >>= 1) se += __shfl_xor_sync(0xffffffffu, se, o);
        float inv = 1.0f / se;
        // disttot = sum of rounded probabilities
        float dt = 0.0f;
        for (int j = lane; j < n; j += 32) dt += Prow[j] * inv;
#pragma unroll
        for (int o = 16; o; o >>= 1) dt += __shfl_xor_sync(0xffffffffu, dt, o);

        // cumsum scan + effect + alibi, track max2
        float carry = 0.0f, mx2 = -3.0e38f;
        for (int jb = 0; jb < n; jb += 32) {
            int j = jb + lane;
            float v = (j < n) ? Prow[j] * inv : 0.0f;
            float x = v;
#pragma unroll
            for (int o = 1; o < 32; o <<= 1) {
                float y = __shfl_up_sync(0xffffffffu, x, o);
                if (lane >= o) x += y;
            }
            if (j < n) {
                float cum = x + carry;
                float suf = dt - cum;
                float pos = (float)(gi - j);
                float d2 = fmaxf(suf, 0.0f) * pos;
                float eff;
                if (g2 * d2 > 132.6f) {
                    eff = 1e-5f;                      // exp(dist*g) < 1e-5 -> clip
                } else {
                    eff = fmaxf(__expf(g * sqrtf(d2)), 1e-5f);
                }
                float s2 = Srow[j] * eff + slope * (float)j;
                Srow[j] = s2;
                mx2 = fmaxf(mx2, s2);
            }
            carry += __shfl_sync(0xffffffffu, x, 31);
        }
#pragma unroll
        for (int o = 16; o; o >>= 1) mx2 = fmaxf(mx2, __shfl_xor_sync(0xffffffffu, mx2, o));

        // softmax2
        float se2 = 0.0f;
        for (int j = lane; j < n; j += 32) {
            float dlt = Srow[j] - mx2;
            float e2 = (dlt > -87.3f) ? __expf(dlt) : 0.0f;
            Prow[j] = e2; se2 += e2;
        }
#pragma unroll
        for (int o = 16; o; o >>= 1) se2 += __shfl_xor_sync(0xffffffffu, se2, o);
        float inv2 = 1.0f / se2;

        float* arow = attn_out + ((size_t)bh << 20) + ((size_t)gi << 10);
        for (int j = lane; j < 1024; j += 32) {
            float a = (j < n) ? Prow[j] * inv2 : 0.0f;
            arow[j] = a;                 // full row incl. causal zeros (out is poisoned)
            if (j < jpad) Srow[j] = a;   // smem copy for the AV GEMM
        }
    }
    __syncthreads();

    // ---- out = attn @ V ----
    float o0 = 0, o1 = 0, o2 = 0, o3 = 0;
    for (int jt = 0; jt <= jtMax; jt++) {
        int j0 = jt << 7;
        for (int e = tid; e < 128 * 64; e += 256) {
            int j = e >> 6, dk = e & 63;
            KVs[j * 65 + dk] = vp[(size_t)((b << 10) + j0 + j) * Dd + (h << 6) + dk];
        }
        __syncthreads();
#pragma unroll 4
        for (int jj = 0; jj < 128; jj++) {
            float vv = KVs[jj * 65 + c];
            o0 += Ssm[r4 * 1024 + j0 + jj] * vv;
            o1 += Ssm[(r4 + 4) * 1024 + j0 + jj] * vv;
            o2 += Ssm[(r4 + 8) * 1024 + j0 + jj] * vv;
            o3 += Ssm[(r4 + 12) * 1024 + j0 + jj] * vv;
        }
        __syncthreads();
    }
    op[(size_t)((b << 10) + i0 + r4) * Dd + (h << 6) + c] = o0;
    op[(size_t)((b << 10) + i0 + r4 + 4) * Dd + (h << 6) + c] = o1;
    op[(size_t)((b << 10) + i0 + r4 + 8) * Dd + (h << 6) + c] = o2;
    op[(size_t)((b << 10) + i0 + r4 + 12) * Dd + (h << 6) + c] = o3;
}

// ---------------- launch ----------------
extern "C" void kernel_launch(void* const* d_in, const int* in_sizes, int n_in,
                              void* d_out, int out_size) {
    const float* q      = (const float*)d_in[0];
    const float* k      = (const float*)d_in[1];
    const float* v      = (const float*)d_in[2];
    // d_in[3] = mask (tril causal) — structure used implicitly
    const float* Wq     = (const float*)d_in[4];
    const float* bq     = (const float*)d_in[5];
    const float* Wv     = (const float*)d_in[6];
    const float* bv     = (const float*)d_in[7];
    const float* Wo     = (const float*)d_in[8];
    const float* bo     = (const float*)d_in[9];
    const float* gammas = (const float*)d_in[10];

    float* out  = (float*)d_out;                       // [B,S,D]
    float* attn = out + (size_t)Mrows * Dd;            // [B,H,S,S]

    float *qp, *kp, *vp, *op;
    cudaGetSymbolAddress((void**)&qp, g_qp);
    cudaGetSymbolAddress((void**)&kp, g_kp);
    cudaGetSymbolAddress((void**)&vp, g_vp);
    cudaGetSymbolAddress((void**)&op, g_op);

    const int ATTN_SMEM = (16 * 1024 * 2 + 16 * 64 + 8320) * 4;  // 168448 B
    cudaFuncSetAttribute(attn_kernel, cudaFuncAttributeMaxDynamicSharedMemorySize,
                         ATTN_SMEM);

    freq_init_kernel<<<1, 32>>>();

    dim3 ggrid(8, 64);   // N/64, M/64
    gemm_bias_kernel<<<ggrid, 256>>>(q, Wq, bq, qp);
    gemm_bias_kernel<<<ggrid, 256>>>(k, Wq, bq, kp);   // kq_same: K uses Wq/bq
    gemm_bias_kernel<<<ggrid, 256>>>(v, Wv, bv, vp);

    rope_kernel<<<8192, 256>>>(qp, kp);

    attn_kernel<<<dim3(64, 32), 256, ATTN_SMEM>>>(qp, kp, vp, gammas, attn, op);

    gemm_bias_kernel<<<ggrid, 256>>>(op, Wo, bo, out);
}

// round 2
// speedup vs baseline: 1.6700x; 1.6700x over previous
#include <cuda_runtime.h>
#include <math.h>

#define Bb 4
#define Ss 1024
#define Dd 512
#define Hh 8
#define DKk 64
#define Mrows 4096   // B*S

// ---------------- scratch (no allocations allowed) ----------------
__device__ float g_qp[Mrows * Dd];
__device__ float g_kp[Mrows * Dd];
__device__ float g_vp[Mrows * Dd];
__device__ float g_op[Mrows * Dd];
__device__ float g_freq[32];

// ---------------- RoPE frequency table ----------------
__global__ void freq_init_kernel() {
    int t = threadIdx.x;
    if (t < 32) {
        g_freq[t] = (float)exp(-((double)(2 * t) / 64.0) * log(10000.0));
    }
}

// ---------------- GEMM: C[M,N] = A[M,K] @ W[N,K]^T + bias ----------------
// 64x64 tile, BK=16, 128 threads, 8x4 microtile, k-major smem, float4 loads.
__global__ __launch_bounds__(128) void gemm_bias_kernel(
    const float* __restrict__ A, const float* __restrict__ W,
    const float* __restrict__ bias, float* __restrict__ C) {
    __shared__ __align__(16) float As[16 * 68];
    __shared__ __align__(16) float Bs[16 * 68];
    const int tid = threadIdx.x;
    const int tx = tid & 15, ty = tid >> 4;
    const int rowBase = blockIdx.y << 6;
    const int colBase = blockIdx.x << 6;
    float acc[8][4] = {};
    for (int kt = 0; kt < 512; kt += 16) {
#pragma unroll
        for (int l = 0; l < 2; l++) {
            int e = tid + (l << 7);
            int r = e >> 2, kq = (e & 3) << 2;
            float4 va = *(const float4*)&A[(size_t)(rowBase + r) * 512 + kt + kq];
            As[(kq + 0) * 68 + r] = va.x;
            As[(kq + 1) * 68 + r] = va.y;
            As[(kq + 2) * 68 + r] = va.z;
            As[(kq + 3) * 68 + r] = va.w;
            float4 vb = *(const float4*)&W[(size_t)(colBase + r) * 512 + kt + kq];
            Bs[(kq + 0) * 68 + r] = vb.x;
            Bs[(kq + 1) * 68 + r] = vb.y;
            Bs[(kq + 2) * 68 + r] = vb.z;
            Bs[(kq + 3) * 68 + r] = vb.w;
        }
        __syncthreads();
#pragma unroll
        for (int kk = 0; kk < 16; kk++) {
            float4 a0 = *(const float4*)&As[kk * 68 + (ty << 3)];
            float4 a1 = *(const float4*)&As[kk * 68 + (ty << 3) + 4];
            float4 b0 = *(const float4*)&Bs[kk * 68 + (tx << 2)];
            float av[8] = {a0.x, a0.y, a0.z, a0.w, a1.x, a1.y, a1.z, a1.w};
            float bv[4] = {b0.x, b0.y, b0.z, b0.w};
#pragma unroll
            for (int i = 0; i < 8; i++)
#pragma unroll
                for (int j = 0; j < 4; j++) acc[i][j] += av[i] * bv[j];
        }
        __syncthreads();
    }
    float4 b4 = *(const float4*)&bias[colBase + (tx << 2)];
#pragma unroll
    for (int i = 0; i < 8; i++) {
        int row = rowBase + (ty << 3) + i;
        float4 o = make_float4(acc[i][0] + b4.x, acc[i][1] + b4.y,
                               acc[i][2] + b4.z, acc[i][3] + b4.w);
        *(float4*)&C[(size_t)row * 512 + colBase + (tx << 2)] = o;
    }
}

// ---------------- RoPE in place on [B*S, D] projected q/k ----------------
__global__ __launch_bounds__(256) void rope_kernel(float* qp, float* kp) {
    int idx = blockIdx.x * 256 + threadIdx.x;   // 2 * 4096 * 256 threads
    float* x = (idx >= (Mrows * 256)) ? kp : qp;
    int rem = idx & (Mrows * 256 - 1);
    int row = rem >> 8;        // b*S + s
    int pr = rem & 255;        // pair index within row: h*32 + t
    int s = row & (Ss - 1);
    int t = pr & 31;
    int h = pr >> 5;
    float ang = (float)s * g_freq[t];
    float sv, cv;
    sincosf(ang, &sv, &cv);
    size_t base = (size_t)row * Dd + (h << 6) + (t << 1);
    float x0 = x[base], x1 = x[base + 1];
    x[base]     = x0 * cv - x1 * sv;
    x[base + 1] = x1 * cv + x0 * sv;
}

// ---------------- fused attention ----------------
// block = 16 query rows of one (b,h). 256 threads, 2 CTAs/SM.
// smem: Ssm[16][1024] scores/attn, Qs[16][68], KV[128][68] (K then V).
__global__ __launch_bounds__(256, 2) void attn_kernel(
    const float* __restrict__ qp, const float* __restrict__ kp,
    const float* __restrict__ vp, const float* __restrict__ gammas,
    float* __restrict__ attn_out, float* __restrict__ op) {
    extern __shared__ __align__(16) float sm[];
    float* Ssm = sm;                  // 16*1024
    float* Qs  = sm + 16 * 1024;      // 16*68
    float* KV  = Qs + 16 * 68;        // 128*68

    const int tid = threadIdx.x;
    const int bh = blockIdx.y, b = bh >> 3, h = bh & 7;
    const int i0 = blockIdx.x << 4;
    const int r4 = tid >> 6, c = tid & 63;
    const int jtMax = (i0 + 15) >> 7;

    // load+scale Q tile (one float4 per thread)
    {
        int r = tid >> 4, dq = (tid & 15) << 2;
        float4 v = *(const float4*)&qp[(size_t)((b << 10) + i0 + r) * 512 + (h << 6) + dq];
        v.x *= 0.125f; v.y *= 0.125f; v.z *= 0.125f; v.w *= 0.125f;
        *(float4*)&Qs[r * 68 + dq] = v;
    }
    __syncthreads();

    // ---- scores = Q K^T (scaled), 128-wide j tiles ----
    for (int jt = 0; jt <= jtMax; jt++) {
        int j0 = jt << 7;
#pragma unroll
        for (int l = 0; l < 8; l++) {
            int e = tid + (l << 8);
            int j = e >> 4, dq = (e & 15) << 2;
            *(float4*)&KV[j * 68 + dq] =
                *(const float4*)&kp[(size_t)((b << 10) + j0 + j) * 512 + (h << 6) + dq];
        }
        __syncthreads();
        float a00 = 0, a01 = 0, a10 = 0, a11 = 0, a20 = 0, a21 = 0, a30 = 0, a31 = 0;
#pragma unroll
        for (int dq = 0; dq < 64; dq += 4) {
            float4 k0 = *(const float4*)&KV[c * 68 + dq];
            float4 k1 = *(const float4*)&KV[(c + 64) * 68 + dq];
            float4 q0 = *(const float4*)&Qs[r4 * 68 + dq];
            float4 q1 = *(const float4*)&Qs[(r4 + 4) * 68 + dq];
            float4 q2 = *(const float4*)&Qs[(r4 + 8) * 68 + dq];
            float4 q3 = *(const float4*)&Qs[(r4 + 12) * 68 + dq];
            a00 += q0.x * k0.x + q0.y * k0.y + q0.z * k0.z + q0.w * k0.w;
            a01 += q0.x * k1.x + q0.y * k1.y + q0.z * k1.z + q0.w * k1.w;
            a10 += q1.x * k0.x + q1.y * k0.y + q1.z * k0.z + q1.w * k0.w;
            a11 += q1.x * k1.x + q1.y * k1.y + q1.z * k1.z + q1.w * k1.w;
            a20 += q2.x * k0.x + q2.y * k0.y + q2.z * k0.z + q2.w * k0.w;
            a21 += q2.x * k1.x + q2.y * k1.y + q2.z * k1.z + q2.w * k1.w;
            a30 += q3.x * k0.x + q3.y * k0.y + q3.z * k0.z + q3.w * k0.w;
            a31 += q3.x * k1.x + q3.y * k1.y + q3.z * k1.z + q3.w * k1.w;
        }
        Ssm[r4 * 1024 + j0 + c] = a00;          Ssm[r4 * 1024 + j0 + c + 64] = a01;
        Ssm[(r4 + 4) * 1024 + j0 + c] = a10;    Ssm[(r4 + 4) * 1024 + j0 + c + 64] = a11;
        Ssm[(r4 + 8) * 1024 + j0 + c] = a20;    Ssm[(r4 + 8) * 1024 + j0 + c + 64] = a21;
        Ssm[(r4 + 12) * 1024 + j0 + c] = a30;   Ssm[(r4 + 12) * 1024 + j0 + c + 64] = a31;
        __syncthreads();
    }

    // ---- row phase: softmax1, cumsum, decay gate, ALiBi, softmax2, attn write ----
    const int warp = tid >> 5, lane = tid & 31;
    const float gamma = gammas[h];
    const float g = -(fmaxf(gamma, 0.0f) + log1pf(expf(-fabsf(gamma))));  // -softplus
    const float g2 = g * g;
    const float slope = exp2f(-(float)(h + 1));
    const int jpad = (jtMax + 1) << 7;

    for (int rr = 0; rr < 2; rr++) {
        int r = (warp << 1) + rr;
        int gi = i0 + r;
        int n = gi + 1;
        float* Srow = Ssm + (r << 10);

        // max
        float mx = -3.0e38f;
        for (int j = lane; j < n; j += 32) mx = fmaxf(mx, Srow[j]);
#pragma unroll
        for (int o = 16; o; o >>= 1) mx = fmaxf(mx, __shfl_xor_sync(0xffffffffu, mx, o));
        // sum of exp
        float se = 0.0f;
        for (int j = lane; j < n; j += 32) se += __expf(Srow[j] - mx);
#pragma unroll
        for (int o = 16; o; o >>= 1) se += __shfl_xor_sync(0xffffffffu, se, o);
        float inv = 1.0f / se;
        // disttot = sum of rounded probabilities (recompute exp)
        float dt = 0.0f;
        for (int j = lane; j < n; j += 32) dt += __expf(Srow[j] - mx) * inv;
#pragma unroll
        for (int o = 16; o; o >>= 1) dt += __shfl_xor_sync(0xffffffffu, dt, o);

        // cumsum scan + effect + alibi, track max2
        float carry = 0.0f, mx2 = -3.0e38f;
        for (int jb = 0; jb < n; jb += 32) {
            int j = jb + lane;
            float v = (j < n) ? __expf(Srow[j] - mx) * inv : 0.0f;
            float x = v;
#pragma unroll
            for (int o = 1; o < 32; o <<= 1) {
                float y = __shfl_up_sync(0xffffffffu, x, o);
                if (lane >= o) x += y;
            }
            if (j < n) {
                float cum = x + carry;
                float suf = dt - cum;
                float pos = (float)(gi - j);
                float d2 = fmaxf(suf, 0.0f) * pos;
                float eff;
                if (g2 * d2 > 132.6f) {
                    eff = 1e-5f;                      // exp(dist*g) < 1e-5 -> clip
                } else {
                    eff = fmaxf(__expf(g * sqrtf(d2)), 1e-5f);
                }
                float s2 = Srow[j] * eff + slope * (float)j;
                Srow[j] = s2;
                mx2 = fmaxf(mx2, s2);
            }
            carry += __shfl_sync(0xffffffffu, x, 31);
        }
#pragma unroll
        for (int o = 16; o; o >>= 1) mx2 = fmaxf(mx2, __shfl_xor_sync(0xffffffffu, mx2, o));

        // softmax2 sum
        float se2 = 0.0f;
        for (int j = lane; j < n; j += 32) {
            float dlt = Srow[j] - mx2;
            se2 += (dlt > -87.3f) ? __expf(dlt) : 0.0f;
        }
#pragma unroll
        for (int o = 16; o; o >>= 1) se2 += __shfl_xor_sync(0xffffffffu, se2, o);
        float inv2 = 1.0f / se2;

        float* arow = attn_out + ((size_t)bh << 20) + ((size_t)gi << 10);
        for (int j = lane; j < 1024; j += 32) {
            float a = 0.0f;
            if (j < n) {
                float dlt = Srow[j] - mx2;
                a = (dlt > -87.3f) ? __expf(dlt) * inv2 : 0.0f;
            }
            arow[j] = a;                 // full row incl. causal zeros
            if (j < jpad) Srow[j] = a;   // smem copy for the AV GEMM
        }
    }
    __syncthreads();

    // ---- out = attn @ V ----
    float o0 = 0, o1 = 0, o2 = 0, o3 = 0;
    for (int jt = 0; jt <= jtMax; jt++) {
        int j0 = jt << 7;
#pragma unroll
        for (int l = 0; l < 8; l++) {
            int e = tid + (l << 8);
            int j = e >> 4, dq = (e & 15) << 2;
            *(float4*)&KV[j * 68 + dq] =
                *(const float4*)&vp[(size_t)((b << 10) + j0 + j) * 512 + (h << 6) + dq];
        }
        __syncthreads();
#pragma unroll 8
        for (int jq = 0; jq < 128; jq += 4) {
            float4 s0 = *(const float4*)&Ssm[r4 * 1024 + j0 + jq];
            float4 s1 = *(const float4*)&Ssm[(r4 + 4) * 1024 + j0 + jq];
            float4 s2 = *(const float4*)&Ssm[(r4 + 8) * 1024 + j0 + jq];
            float4 s3 = *(const float4*)&Ssm[(r4 + 12) * 1024 + j0 + jq];
            float v0 = KV[(jq + 0) * 68 + c];
            float v1 = KV[(jq + 1) * 68 + c];
            float v2 = KV[(jq + 2) * 68 + c];
            float v3 = KV[(jq + 3) * 68 + c];
            o0 += s0.x * v0 + s0.y * v1 + s0.z * v2 + s0.w * v3;
            o1 += s1.x * v0 + s1.y * v1 + s1.z * v2 + s1.w * v3;
            o2 += s2.x * v0 + s2.y * v1 + s2.z * v2 + s2.w * v3;
            o3 += s3.x * v0 + s3.y * v1 + s3.z * v2 + s3.w * v3;
        }
        __syncthreads();
    }
    op[(size_t)((b << 10) + i0 + r4) * 512 + (h << 6) + c] = o0;
    op[(size_t)((b << 10) + i0 + r4 + 4) * 512 + (h << 6) + c] = o1;
    op[(size_t)((b << 10) + i0 + r4 + 8) * 512 + (h << 6) + c] = o2;
    op[(size_t)((b << 10) + i0 + r4 + 12) * 512 + (h << 6) + c] = o3;
}

// ---------------- launch ----------------
extern "C" void kernel_launch(void* const* d_in, const int* in_sizes, int n_in,
                              void* d_out, int out_size) {
    const float* q      = (const float*)d_in[0];
    const float* k      = (const float*)d_in[1];
    const float* v      = (const float*)d_in[2];
    // d_in[3] = mask (tril causal) — structure used implicitly
    const float* Wq     = (const float*)d_in[4];
    const float* bq     = (const float*)d_in[5];
    const float* Wv     = (const float*)d_in[6];
    const float* bv     = (const float*)d_in[7];
    const float* Wo     = (const float*)d_in[8];
    const float* bo     = (const float*)d_in[9];
    const float* gammas = (const float*)d_in[10];

    float* out  = (float*)d_out;                       // [B,S,D]
    float* attn = out + (size_t)Mrows * Dd;            // [B,H,S,S]

    float *qp, *kp, *vp, *op;
    cudaGetSymbolAddress((void**)&qp, g_qp);
    cudaGetSymbolAddress((void**)&kp, g_kp);
    cudaGetSymbolAddress((void**)&vp, g_vp);
    cudaGetSymbolAddress((void**)&op, g_op);

    const int ATTN_SMEM = (16 * 1024 + 16 * 68 + 128 * 68) * 4;  // 104704 B
    cudaFuncSetAttribute(attn_kernel, cudaFuncAttributeMaxDynamicSharedMemorySize,
                         ATTN_SMEM);

    freq_init_kernel<<<1, 32>>>();

    dim3 ggrid(8, 64);   // N/64, M/64
    gemm_bias_kernel<<<ggrid, 128>>>(q, Wq, bq, qp);
    gemm_bias_kernel<<<ggrid, 128>>>(k, Wq, bq, kp);   // kq_same: K uses Wq/bq
    gemm_bias_kernel<<<ggrid, 128>>>(v, Wv, bv, vp);

    rope_kernel<<<8192, 256>>>(qp, kp);

    attn_kernel<<<dim3(64, 32), 256, ATTN_SMEM>>>(qp, kp, vp, gammas, attn, op);

    gemm_bias_kernel<<<ggrid, 128>>>(op, Wo, bo, out);
}

// round 3
// speedup vs baseline: 1.7709x; 1.0604x over previous
#include <cuda_runtime.h>
#include <math.h>

#define Bb 4
#define Ss 1024
#define Dd 512
#define Hh 8
#define DKk 64
#define Mrows 4096   // B*S

// ---------------- scratch (no allocations allowed) ----------------
__device__ float g_qp[Mrows * Dd];
__device__ float g_kp[Mrows * Dd];
__device__ float g_vp[Mrows * Dd];
__device__ float g_op[Mrows * Dd];
__device__ float g_freq[32];

// ---------------- RoPE frequency table ----------------
__global__ void freq_init_kernel() {
    int t = threadIdx.x;
    if (t < 32) {
        g_freq[t] = (float)exp(-((double)(2 * t) / 64.0) * log(10000.0));
    }
}

// ---------------- tf32 helpers ----------------
__device__ __forceinline__ unsigned f2tf32(float a) {
    unsigned r;
    asm("cvt.rna.tf32.f32 %0, %1;" : "=r"(r) : "f"(a));
    return r;
}

__device__ __forceinline__ void mma_tf32(
    float& c0, float& c1, float& c2, float& c3,
    unsigned a0, unsigned a1, unsigned a2, unsigned a3,
    unsigned b0, unsigned b1) {
    asm volatile(
        "mma.sync.aligned.m16n8k8.row.col.f32.tf32.tf32.f32 "
        "{%0,%1,%2,%3}, {%4,%5,%6,%7}, {%8,%9}, {%0,%1,%2,%3};"
        : "+f"(c0), "+f"(c1), "+f"(c2), "+f"(c3)
        : "r"(a0), "r"(a1), "r"(a2), "r"(a3), "r"(b0), "r"(b1));
}

// ---------------- GEMM: C[M,N] = A[M,K] @ W[N,K]^T + bias (3xTF32 tensor) ----
// Block tile 128x64, 256 threads = 8 warps (4m x 2n), warp tile 32x32, BK=16.
__global__ __launch_bounds__(256) void gemm_bias_kernel(
    const float* __restrict__ A, const float* __restrict__ W,
    const float* __restrict__ bias, float* __restrict__ C) {
    __shared__ __align__(16) float As[128 * 20];
    __shared__ __align__(16) float Bs[64 * 20];
    const int tid = threadIdx.x;
    const int warp = tid >> 5, lane = tid & 31;
    const int g = lane >> 2, t4 = lane & 3;
    const int wm = (warp >> 1) << 5;       // warp m origin within block (0,32,64,96)
    const int wn = (warp & 1) << 5;        // warp n origin within block (0,32)
    const int rowBase = blockIdx.y << 7;
    const int colBase = blockIdx.x << 6;

    float acc[2][4][4];
#pragma unroll
    for (int i = 0; i < 2; i++)
#pragma unroll
        for (int j = 0; j < 4; j++)
#pragma unroll
            for (int kq = 0; kq < 4; kq++) acc[i][j][kq] = 0.0f;

    for (int kt = 0; kt < 512; kt += 16) {
        // load A tile 128x16 (2 float4 per thread), B tile 64x16 (1 float4)
#pragma unroll
        for (int l = 0; l < 2; l++) {
            int e = tid + (l << 8);
            int r = e >> 2, kq = (e & 3) << 2;
            *(float4*)&As[r * 20 + kq] =
                *(const float4*)&A[(size_t)(rowBase + r) * 512 + kt + kq];
        }
        {
            int r = tid >> 2, kq = (tid & 3) << 2;
            *(float4*)&Bs[r * 20 + kq] =
                *(const float4*)&W[(size_t)(colBase + r) * 512 + kt + kq];
        }
        __syncthreads();

#pragma unroll
        for (int ks = 0; ks < 16; ks += 8) {
            // A fragments (2 m-tiles of 16): hi/lo split
            unsigned ah[2][4], al[2][4];
#pragma unroll
            for (int mt = 0; mt < 2; mt++) {
                int r0 = wm + (mt << 4) + g;
                float f0 = As[r0 * 20 + ks + t4];
                float f1 = As[(r0 + 8) * 20 + ks + t4];
                float f2 = As[r0 * 20 + ks + t4 + 4];
                float f3 = As[(r0 + 8) * 20 + ks + t4 + 4];
                ah[mt][0] = f2tf32(f0); al[mt][0] = f2tf32(f0 - __uint_as_float(ah[mt][0]));
                ah[mt][1] = f2tf32(f1); al[mt][1] = f2tf32(f1 - __uint_as_float(ah[mt][1]));
                ah[mt][2] = f2tf32(f2); al[mt][2] = f2tf32(f2 - __uint_as_float(ah[mt][2]));
                ah[mt][3] = f2tf32(f3); al[mt][3] = f2tf32(f3 - __uint_as_float(ah[mt][3]));
            }
#pragma unroll
            for (int nt = 0; nt < 4; nt++) {
                int n0 = wn + (nt << 3) + g;
                float fb0 = Bs[n0 * 20 + ks + t4];
                float fb1 = Bs[n0 * 20 + ks + t4 + 4];
                unsigned bh0 = f2tf32(fb0), bl0 = f2tf32(fb0 - __uint_as_float(bh0));
                unsigned bh1 = f2tf32(fb1), bl1 = f2tf32(fb1 - __uint_as_float(bh1));
#pragma unroll
                for (int mt = 0; mt < 2; mt++) {
                    float* c = acc[mt][nt];
                    mma_tf32(c[0], c[1], c[2], c[3],
                             ah[mt][0], ah[mt][1], ah[mt][2], ah[mt][3], bl0, bl1);
                    mma_tf32(c[0], c[1], c[2], c[3],
                             al[mt][0], al[mt][1], al[mt][2], al[mt][3], bh0, bh1);
                    mma_tf32(c[0], c[1], c[2], c[3],
                             ah[mt][0], ah[mt][1], ah[mt][2], ah[mt][3], bh0, bh1);
                }
            }
        }
        __syncthreads();
    }

    // epilogue: bias + store (float2 per c-pair)
#pragma unroll
    for (int nt = 0; nt < 4; nt++) {
        int col = colBase + wn + (nt << 3) + (t4 << 1);
        float bx = bias[col], by = bias[col + 1];
#pragma unroll
        for (int mt = 0; mt < 2; mt++) {
            int row = rowBase + wm + (mt << 4) + g;
            float* c = acc[mt][nt];
            *(float2*)&C[(size_t)row * 512 + col] = make_float2(c[0] + bx, c[1] + by);
            *(float2*)&C[(size_t)(row + 8) * 512 + col] = make_float2(c[2] + bx, c[3] + by);
        }
    }
}

// ---------------- RoPE in place on [B*S, D] projected q/k ----------------
__global__ __launch_bounds__(256) void rope_kernel(float* qp, float* kp) {
    int idx = blockIdx.x * 256 + threadIdx.x;   // 2 * 4096 * 256 threads
    float* x = (idx >= (Mrows * 256)) ? kp : qp;
    int rem = idx & (Mrows * 256 - 1);
    int row = rem >> 8;        // b*S + s
    int pr = rem & 255;        // pair index within row: h*32 + t
    int s = row & (Ss - 1);
    int t = pr & 31;
    int h = pr >> 5;
    float ang = (float)s * g_freq[t];
    float sv, cv;
    sincosf(ang, &sv, &cv);
    size_t base = (size_t)row * Dd + (h << 6) + (t << 1);
    float x0 = x[base], x1 = x[base + 1];
    x[base]     = x0 * cv - x1 * sv;
    x[base + 1] = x1 * cv + x0 * sv;
}

// ---------------- fused attention ----------------
// block = 16 query rows of one (b,h). 256 threads, 2 CTAs/SM.
__global__ __launch_bounds__(256, 2) void attn_kernel(
    const float* __restrict__ qp, const float* __restrict__ kp,
    const float* __restrict__ vp, const float* __restrict__ gammas,
    float* __restrict__ attn_out, float* __restrict__ op) {
    extern __shared__ __align__(16) float sm[];
    float* Ssm = sm;                  // 16*1024
    float* Qs  = sm + 16 * 1024;      // 16*68
    float* KV  = Qs + 16 * 68;        // 128*68

    const int tid = threadIdx.x;
    const int bh = blockIdx.y, b = bh >> 3, h = bh & 7;
    const int i0 = blockIdx.x << 4;
    const int r4 = tid >> 6, c = tid & 63;
    const int jtMax = (i0 + 15) >> 7;

    // load+scale Q tile (one float4 per thread)
    {
        int r = tid >> 4, dq = (tid & 15) << 2;
        float4 v = *(const float4*)&qp[(size_t)((b << 10) + i0 + r) * 512 + (h << 6) + dq];
        v.x *= 0.125f; v.y *= 0.125f; v.z *= 0.125f; v.w *= 0.125f;
        *(float4*)&Qs[r * 68 + dq] = v;
    }
    __syncthreads();

    // ---- scores = Q K^T (scaled), 128-wide j tiles ----
    for (int jt = 0; jt <= jtMax; jt++) {
        int j0 = jt << 7;
#pragma unroll
        for (int l = 0; l < 8; l++) {
            int e = tid + (l << 8);
            int j = e >> 4, dq = (e & 15) << 2;
            *(float4*)&KV[j * 68 + dq] =
                *(const float4*)&kp[(size_t)((b << 10) + j0 + j) * 512 + (h << 6) + dq];
        }
        __syncthreads();
        float a00 = 0, a01 = 0, a10 = 0, a11 = 0, a20 = 0, a21 = 0, a30 = 0, a31 = 0;
#pragma unroll
        for (int dq = 0; dq < 64; dq += 4) {
            float4 k0 = *(const float4*)&KV[c * 68 + dq];
            float4 k1 = *(const float4*)&KV[(c + 64) * 68 + dq];
            float4 q0 = *(const float4*)&Qs[r4 * 68 + dq];
            float4 q1 = *(const float4*)&Qs[(r4 + 4) * 68 + dq];
            float4 q2 = *(const float4*)&Qs[(r4 + 8) * 68 + dq];
            float4 q3 = *(const float4*)&Qs[(r4 + 12) * 68 + dq];
            a00 += q0.x * k0.x + q0.y * k0.y + q0.z * k0.z + q0.w * k0.w;
            a01 += q0.x * k1.x + q0.y * k1.y + q0.z * k1.z + q0.w * k1.w;
            a10 += q1.x * k0.x + q1.y * k0.y + q1.z * k0.z + q1.w * k0.w;
            a11 += q1.x * k1.x + q1.y * k1.y + q1.z * k1.z + q1.w * k1.w;
            a20 += q2.x * k0.x + q2.y * k0.y + q2.z * k0.z + q2.w * k0.w;
            a21 += q2.x * k1.x + q2.y * k1.y + q2.z * k1.z + q2.w * k1.w;
            a30 += q3.x * k0.x + q3.y * k0.y + q3.z * k0.z + q3.w * k0.w;
            a31 += q3.x * k1.x + q3.y * k1.y + q3.z * k1.z + q3.w * k1.w;
        }
        Ssm[r4 * 1024 + j0 + c] = a00;          Ssm[r4 * 1024 + j0 + c + 64] = a01;
        Ssm[(r4 + 4) * 1024 + j0 + c] = a10;    Ssm[(r4 + 4) * 1024 + j0 + c + 64] = a11;
        Ssm[(r4 + 8) * 1024 + j0 + c] = a20;    Ssm[(r4 + 8) * 1024 + j0 + c + 64] = a21;
        Ssm[(r4 + 12) * 1024 + j0 + c] = a30;   Ssm[(r4 + 12) * 1024 + j0 + c + 64] = a31;
        __syncthreads();
    }

    // ---- row phase: softmax1, cumsum, decay gate, ALiBi, softmax2, attn write ----
    const int warp = tid >> 5, lane = tid & 31;
    const float gamma = gammas[h];
    const float g = -(fmaxf(gamma, 0.0f) + log1pf(expf(-fabsf(gamma))));  // -softplus
    const float g2 = g * g;
    const float slope = exp2f(-(float)(h + 1));
    const int jpad = (jtMax + 1) << 7;

    for (int rr = 0; rr < 2; rr++) {
        int r = (warp << 1) + rr;
        int gi = i0 + r;
        int n = gi + 1;
        float* Srow = Ssm + (r << 10);

        // max
        float mx = -3.0e38f;
        for (int j = lane; j < n; j += 32) mx = fmaxf(mx, Srow[j]);
#pragma unroll
        for (int o = 16; o; o >>= 1) mx = fmaxf(mx, __shfl_xor_sync(0xffffffffu, mx, o));
        // sum of exp
        float se = 0.0f;
        for (int j = lane; j < n; j += 32) se += __expf(Srow[j] - mx);
#pragma unroll
        for (int o = 16; o; o >>= 1) se += __shfl_xor_sync(0xffffffffu, se, o);
        float inv = 1.0f / se;
        // disttot = sum of rounded probabilities (recompute exp)
        float dt = 0.0f;
        for (int j = lane; j < n; j += 32) dt += __expf(Srow[j] - mx) * inv;
#pragma unroll
        for (int o = 16; o; o >>= 1) dt += __shfl_xor_sync(0xffffffffu, dt, o);

        // cumsum scan + effect + alibi, track max2
        float carry = 0.0f, mx2 = -3.0e38f;
        for (int jb = 0; jb < n; jb += 32) {
            int j = jb + lane;
            float v = (j < n) ? __expf(Srow[j] - mx) * inv : 0.0f;
            float x = v;
#pragma unroll
            for (int o = 1; o < 32; o <<= 1) {
                float y = __shfl_up_sync(0xffffffffu, x, o);
                if (lane >= o) x += y;
            }
            if (j < n) {
                float cum = x + carry;
                float suf = dt - cum;
                float pos = (float)(gi - j);
                float d2 = fmaxf(suf, 0.0f) * pos;
                float eff;
                if (g2 * d2 > 132.6f) {
                    eff = 1e-5f;                      // exp(dist*g) < 1e-5 -> clip
                } else {
                    eff = fmaxf(__expf(g * sqrtf(d2)), 1e-5f);
                }
                float s2 = Srow[j] * eff + slope * (float)j;
                Srow[j] = s2;
                mx2 = fmaxf(mx2, s2);
            }
            carry += __shfl_sync(0xffffffffu, x, 31);
        }
#pragma unroll
        for (int o = 16; o; o >>= 1) mx2 = fmaxf(mx2, __shfl_xor_sync(0xffffffffu, mx2, o));

        // softmax2 sum (store exp in place — score no longer needed)
        float se2 = 0.0f;
        for (int j = lane; j < n; j += 32) {
            float dlt = Srow[j] - mx2;
            float e2 = (dlt > -87.3f) ? __expf(dlt) : 0.0f;
            Srow[j] = e2;
            se2 += e2;
        }
#pragma unroll
        for (int o = 16; o; o >>= 1) se2 += __shfl_xor_sync(0xffffffffu, se2, o);
        float inv2 = 1.0f / se2;

        float* arow = attn_out + ((size_t)bh << 20) + ((size_t)gi << 10);
        for (int j = lane; j < 1024; j += 32) {
            float a = (j < n) ? Srow[j] * inv2 : 0.0f;
            arow[j] = a;                 // full row incl. causal zeros
            if (j < jpad) Srow[j] = a;   // smem copy for the AV GEMM
        }
    }
    __syncthreads();

    // ---- out = attn @ V ----
    float o0 = 0, o1 = 0, o2 = 0, o3 = 0;
    for (int jt = 0; jt <= jtMax; jt++) {
        int j0 = jt << 7;
#pragma unroll
        for (int l = 0; l < 8; l++) {
            int e = tid + (l << 8);
            int j = e >> 4, dq = (e & 15) << 2;
            *(float4*)&KV[j * 68 + dq] =
                *(const float4*)&vp[(size_t)((b << 10) + j0 + j) * 512 + (h << 6) + dq];
        }
        __syncthreads();
#pragma unroll 8
        for (int jq = 0; jq < 128; jq += 4) {
            float4 s0 = *(const float4*)&Ssm[r4 * 1024 + j0 + jq];
            float4 s1 = *(const float4*)&Ssm[(r4 + 4) * 1024 + j0 + jq];
            float4 s2 = *(const float4*)&Ssm[(r4 + 8) * 1024 + j0 + jq];
            float4 s3 = *(const float4*)&Ssm[(r4 + 12) * 1024 + j0 + jq];
            float v0 = KV[(jq + 0) * 68 + c];
            float v1 = KV[(jq + 1) * 68 + c];
            float v2 = KV[(jq + 2) * 68 + c];
            float v3 = KV[(jq + 3) * 68 + c];
            o0 += s0.x * v0 + s0.y * v1 + s0.z * v2 + s0.w * v3;
            o1 += s1.x * v0 + s1.y * v1 + s1.z * v2 + s1.w * v3;
            o2 += s2.x * v0 + s2.y * v1 + s2.z * v2 + s2.w * v3;
            o3 += s3.x * v0 + s3.y * v1 + s3.z * v2 + s3.w * v3;
        }
        __syncthreads();
    }
    op[(size_t)((b << 10) + i0 + r4) * 512 + (h << 6) + c] = o0;
    op[(size_t)((b << 10) + i0 + r4 + 4) * 512 + (h << 6) + c] = o1;
    op[(size_t)((b << 10) + i0 + r4 + 8) * 512 + (h << 6) + c] = o2;
    op[(size_t)((b << 10) + i0 + r4 + 12) * 512 + (h << 6) + c] = o3;
}

// ---------------- launch ----------------
extern "C" void kernel_launch(void* const* d_in, const int* in_sizes, int n_in,
                              void* d_out, int out_size) {
    const float* q      = (const float*)d_in[0];
    const float* k      = (const float*)d_in[1];
    const float* v      = (const float*)d_in[2];
    // d_in[3] = mask (tril causal) — structure used implicitly
    const float* Wq     = (const float*)d_in[4];
    const float* bq     = (const float*)d_in[5];
    const float* Wv     = (const float*)d_in[6];
    const float* bv     = (const float*)d_in[7];
    const float* Wo     = (const float*)d_in[8];
    const float* bo     = (const float*)d_in[9];
    const float* gammas = (const float*)d_in[10];

    float* out  = (float*)d_out;                       // [B,S,D]
    float* attn = out + (size_t)Mrows * Dd;            // [B,H,S,S]

    float *qp, *kp, *vp, *op;
    cudaGetSymbolAddress((void**)&qp, g_qp);
    cudaGetSymbolAddress((void**)&kp, g_kp);
    cudaGetSymbolAddress((void**)&vp, g_vp);
    cudaGetSymbolAddress((void**)&op, g_op);

    const int ATTN_SMEM = (16 * 1024 + 16 * 68 + 128 * 68) * 4;  // 104704 B
    cudaFuncSetAttribute(attn_kernel, cudaFuncAttributeMaxDynamicSharedMemorySize,
                         ATTN_SMEM);

    freq_init_kernel<<<1, 32>>>();

    dim3 ggrid(8, 32);   // N/64, M/128
    gemm_bias_kernel<<<ggrid, 256>>>(q, Wq, bq, qp);
    gemm_bias_kernel<<<ggrid, 256>>>(k, Wq, bq, kp);   // kq_same: K uses Wq/bq
    gemm_bias_kernel<<<ggrid, 256>>>(v, Wv, bv, vp);

    rope_kernel<<<8192, 256>>>(qp, kp);

    attn_kernel<<<dim3(64, 32), 256, ATTN_SMEM>>>(qp, kp, vp, gammas, attn, op);

    gemm_bias_kernel<<<ggrid, 256>>>(op, Wo, bo, out);
}

// round 4
// speedup vs baseline: 1.8299x; 1.0333x over previous
#include <cuda_runtime.h>
#include <math.h>

#define Bb 4
#define Ss 1024
#define Dd 512
#define Hh 8
#define DKk 64
#define Mrows 4096   // B*S
#define SST 1028     // Ssm row stride (bank-conflict pad)

// ---------------- scratch (no allocations allowed) ----------------
__device__ float g_qp[Mrows * Dd];
__device__ float g_kp[Mrows * Dd];
__device__ float g_vp[Mrows * Dd];
__device__ float g_op[Mrows * Dd];
__device__ float g_freq[32];

// ---------------- RoPE frequency table ----------------
__global__ void freq_init_kernel() {
    int t = threadIdx.x;
    if (t < 32) {
        g_freq[t] = (float)exp(-((double)(2 * t) / 64.0) * log(10000.0));
    }
}

// ---------------- tf32 helpers ----------------
__device__ __forceinline__ unsigned f2tf32(float a) {
    unsigned r;
    asm("cvt.rna.tf32.f32 %0, %1;" : "=r"(r) : "f"(a));
    return r;
}
__device__ __forceinline__ void split1(float f, unsigned& h, unsigned& l) {
    h = f2tf32(f);
    l = f2tf32(f - __uint_as_float(h));
}

__device__ __forceinline__ void mma_tf32(
    float& c0, float& c1, float& c2, float& c3,
    unsigned a0, unsigned a1, unsigned a2, unsigned a3,
    unsigned b0, unsigned b1) {
    asm volatile(
        "mma.sync.aligned.m16n8k8.row.col.f32.tf32.tf32.f32 "
        "{%0,%1,%2,%3}, {%4,%5,%6,%7}, {%8,%9}, {%0,%1,%2,%3};"
        : "+f"(c0), "+f"(c1), "+f"(c2), "+f"(c3)
        : "r"(a0), "r"(a1), "r"(a2), "r"(a3), "r"(b0), "r"(b1));
}

// ---------------- GEMM: C[M,N] = A[M,K] @ W[N,K]^T + bias, opt fused RoPE ----
// Block tile 64x64, 128 threads = 4 warps (2m x 2n), warp tile 32x32, BK=16.
// hi/lo tf32 split done once at smem-store time; inner loop is LDS+MMA only.
__global__ __launch_bounds__(128) void gemm_bias_kernel(
    const float* __restrict__ A, const float* __restrict__ W,
    const float* __restrict__ bias, float* __restrict__ C, int rope) {
    __shared__ __align__(16) unsigned AsH[64 * 20], AsL[64 * 20];
    __shared__ __align__(16) unsigned BsH[64 * 20], BsL[64 * 20];
    const int tid = threadIdx.x;
    const int warp = tid >> 5, lane = tid & 31;
    const int g = lane >> 2, t4 = lane & 3;
    const int wm = (warp >> 1) << 5;       // 0 or 32
    const int wn = (warp & 1) << 5;        // 0 or 32
    const int rowBase = blockIdx.y << 6;
    const int colBase = blockIdx.x << 6;

    float acc[2][4][4];
#pragma unroll
    for (int i = 0; i < 2; i++)
#pragma unroll
        for (int j = 0; j < 4; j++)
#pragma unroll
            for (int kq = 0; kq < 4; kq++) acc[i][j][kq] = 0.0f;

    // prefetch first tiles (2 A float4 + 2 B float4 per thread)
    float4 pa[2], pb[2];
#pragma unroll
    for (int l = 0; l < 2; l++) {
        int e = tid + (l << 7);
        int r = e >> 2, kq = (e & 3) << 2;
        pa[l] = *(const float4*)&A[(size_t)(rowBase + r) * 512 + kq];
        pb[l] = *(const float4*)&W[(size_t)(colBase + r) * 512 + kq];
    }

    for (int kt = 0; kt < 512; kt += 16) {
        // split + store prefetched tile
#pragma unroll
        for (int l = 0; l < 2; l++) {
            int e = tid + (l << 7);
            int r = e >> 2, kq = (e & 3) << 2;
            float av[4] = {pa[l].x, pa[l].y, pa[l].z, pa[l].w};
            float bv[4] = {pb[l].x, pb[l].y, pb[l].z, pb[l].w};
#pragma unroll
            for (int u = 0; u < 4; u++) {
                split1(av[u], AsH[r * 20 + kq + u], AsL[r * 20 + kq + u]);
                split1(bv[u], BsH[r * 20 + kq + u], BsL[r * 20 + kq + u]);
            }
        }
        __syncthreads();
        if (kt + 16 < 512) {
#pragma unroll
            for (int l = 0; l < 2; l++) {
                int e = tid + (l << 7);
                int r = e >> 2, kq = (e & 3) << 2;
                pa[l] = *(const float4*)&A[(size_t)(rowBase + r) * 512 + kt + 16 + kq];
                pb[l] = *(const float4*)&W[(size_t)(colBase + r) * 512 + kt + 16 + kq];
            }
        }
#pragma unroll
        for (int ks = 0; ks < 16; ks += 8) {
            unsigned ah[2][4], al[2][4];
#pragma unroll
            for (int mt = 0; mt < 2; mt++) {
                int r0 = wm + (mt << 4) + g;
                ah[mt][0] = AsH[r0 * 20 + ks + t4];
                ah[mt][1] = AsH[(r0 + 8) * 20 + ks + t4];
                ah[mt][2] = AsH[r0 * 20 + ks + t4 + 4];
                ah[mt][3] = AsH[(r0 + 8) * 20 + ks + t4 + 4];
                al[mt][0] = AsL[r0 * 20 + ks + t4];
                al[mt][1] = AsL[(r0 + 8) * 20 + ks + t4];
                al[mt][2] = AsL[r0 * 20 + ks + t4 + 4];
                al[mt][3] = AsL[(r0 + 8) * 20 + ks + t4 + 4];
            }
#pragma unroll
            for (int nt = 0; nt < 4; nt++) {
                int n0 = wn + (nt << 3) + g;
                unsigned bh0 = BsH[n0 * 20 + ks + t4];
                unsigned bh1 = BsH[n0 * 20 + ks + t4 + 4];
                unsigned bl0 = BsL[n0 * 20 + ks + t4];
                unsigned bl1 = BsL[n0 * 20 + ks + t4 + 4];
#pragma unroll
                for (int mt = 0; mt < 2; mt++) {
                    float* c = acc[mt][nt];
                    mma_tf32(c[0], c[1], c[2], c[3],
                             ah[mt][0], ah[mt][1], ah[mt][2], ah[mt][3], bl0, bl1);
                    mma_tf32(c[0], c[1], c[2], c[3],
                             al[mt][0], al[mt][1], al[mt][2], al[mt][3], bh0, bh1);
                    mma_tf32(c[0], c[1], c[2], c[3],
                             ah[mt][0], ah[mt][1], ah[mt][2], ah[mt][3], bh0, bh1);
                }
            }
        }
        __syncthreads();
    }

    // epilogue: bias (+ optional RoPE on the (even,odd) pair) + store
#pragma unroll
    for (int nt = 0; nt < 4; nt++) {
        int col = colBase + wn + (nt << 3) + (t4 << 1);
        float bx = bias[col], by = bias[col + 1];
        int p = (col & 63) >> 1;           // rope pair index within head
        float fr = g_freq[p];
#pragma unroll
        for (int mt = 0; mt < 2; mt++) {
            int row = rowBase + wm + (mt << 4) + g;
            float* c = acc[mt][nt];
            float x0 = c[0] + bx, x1 = c[1] + by;
            float y0 = c[2] + bx, y1 = c[3] + by;
            if (rope) {
                float sv, cv;
                sincosf((float)(row & 1023) * fr, &sv, &cv);
                float t0 = x0 * cv - x1 * sv;
                x1 = x1 * cv + x0 * sv; x0 = t0;
                sincosf((float)((row + 8) & 1023) * fr, &sv, &cv);
                float u0 = y0 * cv - y1 * sv;
                y1 = y1 * cv + y0 * sv; y0 = u0;
            }
            *(float2*)&C[(size_t)row * 512 + col] = make_float2(x0, x1);
            *(float2*)&C[(size_t)(row + 8) * 512 + col] = make_float2(y0, y1);
        }
    }
}

// ---------------- fused attention ----------------
// block = 16 query rows of one (b,h). 256 threads, 2 CTAs/SM.
// smem: Ssm[16][1028], QH/QL[16][68] (tf32 hi/lo), KV[128][68].
__global__ __launch_bounds__(256, 2) void attn_kernel(
    const float* __restrict__ qp, const float* __restrict__ kp,
    const float* __restrict__ vp, const float* __restrict__ gammas,
    float* __restrict__ attn_out, float* __restrict__ op) {
    extern __shared__ __align__(16) float sm[];
    float* Ssm = sm;                                   // 16*1028
    unsigned* QH = (unsigned*)(sm + 16 * SST);         // 16*68
    unsigned* QL = QH + 16 * 68;                       // 16*68
    float* KV = (float*)(QL + 16 * 68);                // 128*68

    const int tid = threadIdx.x;
    const int bh = blockIdx.y, b = bh >> 3, h = bh & 7;
    const int i0 = blockIdx.x << 4;
    const int r4 = tid >> 6, c = tid & 63;
    const int jtMax = (i0 + 15) >> 7;
    const int warp = tid >> 5, lane = tid & 31;
    const int g = lane >> 2, t4 = lane & 3;

    // load+scale+split Q tile (one float4 per thread)
    {
        int r = tid >> 4, dq = (tid & 15) << 2;
        float4 v = *(const float4*)&qp[(size_t)((b << 10) + i0 + r) * 512 + (h << 6) + dq];
        split1(v.x * 0.125f, QH[r * 68 + dq + 0], QL[r * 68 + dq + 0]);
        split1(v.y * 0.125f, QH[r * 68 + dq + 1], QL[r * 68 + dq + 1]);
        split1(v.z * 0.125f, QH[r * 68 + dq + 2], QL[r * 68 + dq + 2]);
        split1(v.w * 0.125f, QH[r * 68 + dq + 3], QL[r * 68 + dq + 3]);
    }
    __syncthreads();

    // ---- scores = Q K^T via 3xTF32 mma; 128-wide j tiles, warp owns 16 cols ----
    for (int jt = 0; jt <= jtMax; jt++) {
        int j0 = jt << 7;
#pragma unroll
        for (int l = 0; l < 8; l++) {
            int e = tid + (l << 8);
            int j = e >> 4, dq = (e & 15) << 2;
            *(float4*)&KV[j * 68 + dq] =
                *(const float4*)&kp[(size_t)((b << 10) + j0 + j) * 512 + (h << 6) + dq];
        }
        __syncthreads();
        const int jn = (warp << 4);   // warp's 16-col slice within tile
        float acc[2][4] = {};
#pragma unroll
        for (int ks = 0; ks < 64; ks += 8) {
            unsigned ah0 = QH[g * 68 + ks + t4];
            unsigned ah1 = QH[(g + 8) * 68 + ks + t4];
            unsigned ah2 = QH[g * 68 + ks + t4 + 4];
            unsigned ah3 = QH[(g + 8) * 68 + ks + t4 + 4];
            unsigned al0 = QL[g * 68 + ks + t4];
            unsigned al1 = QL[(g + 8) * 68 + ks + t4];
            unsigned al2 = QL[g * 68 + ks + t4 + 4];
            unsigned al3 = QL[(g + 8) * 68 + ks + t4 + 4];
#pragma unroll
            for (int nt = 0; nt < 2; nt++) {
                int j = jn + (nt << 3) + g;
                float kb0 = KV[j * 68 + ks + t4];
                float kb1 = KV[j * 68 + ks + t4 + 4];
                unsigned bh0, bl0, bh1, bl1;
                split1(kb0, bh0, bl0);
                split1(kb1, bh1, bl1);
                float* cc = acc[nt];
                mma_tf32(cc[0], cc[1], cc[2], cc[3], ah0, ah1, ah2, ah3, bl0, bl1);
                mma_tf32(cc[0], cc[1], cc[2], cc[3], al0, al1, al2, al3, bh0, bh1);
                mma_tf32(cc[0], cc[1], cc[2], cc[3], ah0, ah1, ah2, ah3, bh0, bh1);
            }
        }
#pragma unroll
        for (int nt = 0; nt < 2; nt++) {
            int jc = j0 + jn + (nt << 3) + (t4 << 1);
            *(float2*)&Ssm[g * SST + jc] = make_float2(acc[nt][0], acc[nt][1]);
            *(float2*)&Ssm[(g + 8) * SST + jc] = make_float2(acc[nt][2], acc[nt][3]);
        }
        __syncthreads();
    }

    // ---- row phase: softmax1, cumsum, decay gate, ALiBi, softmax2, attn write ----
    const float gamma = gammas[h];
    const float gg = -(fmaxf(gamma, 0.0f) + log1pf(expf(-fabsf(gamma))));  // -softplus
    const float g2 = gg * gg;
    const float slope = exp2f(-(float)(h + 1));
    const int jpad = (jtMax + 1) << 7;

    for (int rr = 0; rr < 2; rr++) {
        int r = (warp << 1) + rr;
        int gi = i0 + r;
        int n = gi + 1;
        float* Srow = Ssm + r * SST;

        // max
        float mx = -3.0e38f;
        for (int j = lane; j < n; j += 32) mx = fmaxf(mx, Srow[j]);
#pragma unroll
        for (int o = 16; o; o >>= 1) mx = fmaxf(mx, __shfl_xor_sync(0xffffffffu, mx, o));
        // sum of exp
        float se = 0.0f;
        for (int j = lane; j < n; j += 32) se += __expf(Srow[j] - mx);
#pragma unroll
        for (int o = 16; o; o >>= 1) se += __shfl_xor_sync(0xffffffffu, se, o);
        float inv = 1.0f / se;
        // disttot = sum of rounded probabilities
        float dt = 0.0f;
        for (int j = lane; j < n; j += 32) dt += __expf(Srow[j] - mx) * inv;
#pragma unroll
        for (int o = 16; o; o >>= 1) dt += __shfl_xor_sync(0xffffffffu, dt, o);

        // cumsum scan + effect + alibi, track max2
        float carry = 0.0f, mx2 = -3.0e38f;
        for (int jb = 0; jb < n; jb += 32) {
            int j = jb + lane;
            float v = (j < n) ? __expf(Srow[j] - mx) * inv : 0.0f;
            float x = v;
#pragma unroll
            for (int o = 1; o < 32; o <<= 1) {
                float y = __shfl_up_sync(0xffffffffu, x, o);
                if (lane >= o) x += y;
            }
            if (j < n) {
                float cum = x + carry;
                float suf = dt - cum;
                float pos = (float)(gi - j);
                float d2 = fmaxf(suf, 0.0f) * pos;
                float eff;
                if (g2 * d2 > 132.6f) {
                    eff = 1e-5f;
                } else {
                    eff = fmaxf(__expf(gg * sqrtf(d2)), 1e-5f);
                }
                float s2 = Srow[j] * eff + slope * (float)j;
                Srow[j] = s2;
                mx2 = fmaxf(mx2, s2);
            }
            carry += __shfl_sync(0xffffffffu, x, 31);
        }
#pragma unroll
        for (int o = 16; o; o >>= 1) mx2 = fmaxf(mx2, __shfl_xor_sync(0xffffffffu, mx2, o));

        // softmax2 sum (store exp in place)
        float se2 = 0.0f;
        for (int j = lane; j < n; j += 32) {
            float dlt = Srow[j] - mx2;
            float e2 = (dlt > -87.3f) ? __expf(dlt) : 0.0f;
            Srow[j] = e2;
            se2 += e2;
        }
#pragma unroll
        for (int o = 16; o; o >>= 1) se2 += __shfl_xor_sync(0xffffffffu, se2, o);
        float inv2 = 1.0f / se2;

        float* arow = attn_out + ((size_t)bh << 20) + ((size_t)gi << 10);
        for (int j = lane; j < 1024; j += 32) {
            float a = (j < n) ? Srow[j] * inv2 : 0.0f;
            arow[j] = a;
            if (j < jpad) Srow[j] = a;
        }
    }
    __syncthreads();

    // ---- out = attn @ V (SIMT fp32) ----
    float o0 = 0, o1 = 0, o2 = 0, o3 = 0;
    for (int jt = 0; jt <= jtMax; jt++) {
        int j0 = jt << 7;
#pragma unroll
        for (int l = 0; l < 8; l++) {
            int e = tid + (l << 8);
            int j = e >> 4, dq = (e & 15) << 2;
            *(float4*)&KV[j * 68 + dq] =
                *(const float4*)&vp[(size_t)((b << 10) + j0 + j) * 512 + (h << 6) + dq];
        }
        __syncthreads();
#pragma unroll 8
        for (int jq = 0; jq < 128; jq += 4) {
            float4 s0 = *(const float4*)&Ssm[r4 * SST + j0 + jq];
            float4 s1 = *(const float4*)&Ssm[(r4 + 4) * SST + j0 + jq];
            float4 s2 = *(const float4*)&Ssm[(r4 + 8) * SST + j0 + jq];
            float4 s3 = *(const float4*)&Ssm[(r4 + 12) * SST + j0 + jq];
            float v0 = KV[(jq + 0) * 68 + c];
            float v1 = KV[(jq + 1) * 68 + c];
            float v2 = KV[(jq + 2) * 68 + c];
            float v3 = KV[(jq + 3) * 68 + c];
            o0 += s0.x * v0 + s0.y * v1 + s0.z * v2 + s0.w * v3;
            o1 += s1.x * v0 + s1.y * v1 + s1.z * v2 + s1.w * v3;
            o2 += s2.x * v0 + s2.y * v1 + s2.z * v2 + s2.w * v3;
            o3 += s3.x * v0 + s3.y * v1 + s3.z * v2 + s3.w * v3;
        }
        __syncthreads();
    }
    op[(size_t)((b << 10) + i0 + r4) * 512 + (h << 6) + c] = o0;
    op[(size_t)((b << 10) + i0 + r4 + 4) * 512 + (h << 6) + c] = o1;
    op[(size_t)((b << 10) + i0 + r4 + 8) * 512 + (h << 6) + c] = o2;
    op[(size_t)((b << 10) + i0 + r4 + 12) * 512 + (h << 6) + c] = o3;
}

// ---------------- launch ----------------
extern "C" void kernel_launch(void* const* d_in, const int* in_sizes, int n_in,
                              void* d_out, int out_size) {
    const float* q      = (const float*)d_in[0];
    const float* k      = (const float*)d_in[1];
    const float* v      = (const float*)d_in[2];
    // d_in[3] = mask (tril causal) — structure used implicitly
    const float* Wq     = (const float*)d_in[4];
    const float* bq     = (const float*)d_in[5];
    const float* Wv     = (const float*)d_in[6];
    const float* bv     = (const float*)d_in[7];
    const float* Wo     = (const float*)d_in[8];
    const float* bo     = (const float*)d_in[9];
    const float* gammas = (const float*)d_in[10];

    float* out  = (float*)d_out;                       // [B,S,D]
    float* attn = out + (size_t)Mrows * Dd;            // [B,H,S,S]

    float *qp, *kp, *vp, *op;
    cudaGetSymbolAddress((void**)&qp, g_qp);
    cudaGetSymbolAddress((void**)&kp, g_kp);
    cudaGetSymbolAddress((void**)&vp, g_vp);
    cudaGetSymbolAddress((void**)&op, g_op);

    const int ATTN_SMEM = (16 * SST + 16 * 68 * 2 + 128 * 68) * 4;  // 109312 B
    cudaFuncSetAttribute(attn_kernel, cudaFuncAttributeMaxDynamicSharedMemorySize,
                         ATTN_SMEM);

    freq_init_kernel<<<1, 32>>>();

    dim3 ggrid(8, 64);   // N/64, M/64
    gemm_bias_kernel<<<ggrid, 128>>>(q, Wq, bq, qp, 1);   // + fused RoPE
    gemm_bias_kernel<<<ggrid, 128>>>(k, Wq, bq, kp, 1);   // kq_same + RoPE
    gemm_bias_kernel<<<ggrid, 128>>>(v, Wv, bv, vp, 0);

    attn_kernel<<<dim3(64, 32), 256, ATTN_SMEM>>>(qp, kp, vp, gammas, attn, op);

    gemm_bias_kernel<<<ggrid, 128>>>(op, Wo, bo, out, 0);
}